// round 7
// baseline (speedup 1.0000x reference)
#include <cuda_runtime.h>
#include <math.h>

// KnnLoss via spatial grid, warp-per-query, register-resident top-8 selection.
// B=2, N=8192 pts uniform in [0,1]^3, KS=16, K=8, radius 0.1.
// Neighbors with dist > 0.1 are replaced by self => contribute 0, so a
// 10x10x10 grid (cell = radius) holds everything that matters.
// Keys: 18-bit fixed-point d2 (monotone quantization of [0, 0.0101]) << 13 | idx.
// (d2, lowest-idx) order == jax.lax.top_k stable rule up to a 3.9e-8 d2 granule.
// Selection: per-lane sorted-4 list + 8 rounds of __reduce_min_sync (REDUX.MIN).
// Deterministic: extraction order is the unique sorted order; sums use fixed trees.

#define B_CONST 2
#define N_CONST 8192
#define KS_CONST 16
#define GRID 10
#define NCELLS (GRID * GRID * GRID)               // 1000
#define TOTPTS (B_CONST * N_CONST)                // 16384
#define R2LIM 0.0101f
#define D2SCALE 25900000.0f                        // 0.0101 * SCALE = 261590 < 2^18
#define RTHRESH_U 259000u                          // floor(0.01 * SCALE)
#define WPB 2                                      // warps (queries) per block
#define MAIN_TPB 64
#define MAIN_BLOCKS (TOTPTS / WPB)                // 8192
#define BUILD_TPB 1024
#define PTS_PER_THREAD (N_CONST / BUILD_TPB)      // 8

__device__ int    g_start [B_CONST * (NCELLS + 1)];
__device__ float4 g_sorted[TOTPTS];               // (x, y, z, idx-as-float-bits)
__device__ float  g_partials[MAIN_BLOCKS];
__device__ int    g_done;

__device__ __forceinline__ int cell_of(float x, float y, float z) {
    int cx = min(max((int)(x * (float)GRID), 0), GRID - 1);
    int cy = min(max((int)(y * (float)GRID), 0), GRID - 1);
    int cz = min(max((int)(z * (float)GRID), 0), GRID - 1);
    return cx + GRID * (cy + GRID * cz);          // x fastest
}

// ---------------- fused grid build: one block per batch ----------------

__global__ __launch_bounds__(BUILD_TPB) void k_build(const float* __restrict__ pc) {
    __shared__ int scnt[BUILD_TPB];
    __shared__ int swoff[32];
    __shared__ int scur[NCELLS];

    const int b    = blockIdx.x;
    const int tid  = threadIdx.x;
    const int lane = tid & 31;
    const int wid  = tid >> 5;
    const float* pcb = pc + (size_t)b * N_CONST * 3;

    scnt[tid] = 0;
    __syncthreads();

    // one global read pass; keep points + cells in registers for the scatter
    float px[PTS_PER_THREAD], py[PTS_PER_THREAD], pz[PTS_PER_THREAD];
    int   pcell[PTS_PER_THREAD];
#pragma unroll
    for (int k = 0; k < PTS_PER_THREAD; ++k) {
        int i = tid + k * BUILD_TPB;
        px[k] = __ldg(pcb + 3 * i + 0);
        py[k] = __ldg(pcb + 3 * i + 1);
        pz[k] = __ldg(pcb + 3 * i + 2);
        pcell[k] = cell_of(px[k], py[k], pz[k]);
    }
#pragma unroll
    for (int k = 0; k < PTS_PER_THREAD; ++k)
        atomicAdd(&scnt[pcell[k]], 1);
    __syncthreads();

    int c = scnt[tid];
    int v = c;
#pragma unroll
    for (int o = 1; o < 32; o <<= 1) {
        int n = __shfl_up_sync(0xFFFFFFFFu, v, o);
        if (lane >= o) v += n;
    }
    if (lane == 31) swoff[wid] = v;
    __syncthreads();
    if (wid == 0) {
        int w = swoff[lane];
#pragma unroll
        for (int o = 1; o < 32; o <<= 1) {
            int n = __shfl_up_sync(0xFFFFFFFFu, w, o);
            if (lane >= o) w += n;
        }
        swoff[lane] = w;
    }
    __syncthreads();
    int incl = v + (wid ? swoff[wid - 1] : 0);
    int excl = incl - c;
    if (tid < NCELLS) {
        g_start[b * (NCELLS + 1) + tid] = excl;
        scur[tid] = excl;
    }
    if (tid == NCELLS - 1) g_start[b * (NCELLS + 1) + NCELLS] = incl;
    if (b == 0 && tid == 0) g_done = 0;
    __syncthreads();

#pragma unroll
    for (int k = 0; k < PTS_PER_THREAD; ++k) {
        int i = tid + k * BUILD_TPB;
        int pos = atomicAdd(&scur[pcell[k]], 1);
        g_sorted[b * N_CONST + pos] = make_float4(px[k], py[k], pz[k], __int_as_float(i));
    }
}

// ---------------- main: warp-per-query knn + loss + fused finalize ----------------

__global__ __launch_bounds__(MAIN_TPB) void knn_loss_main(const float* __restrict__ mask,
                                                          float* __restrict__ out) {
    __shared__ float swacc[WPB];
    __shared__ float sred[MAIN_TPB];
    __shared__ int slast;

    const int warp  = threadIdx.x >> 5;
    const int lane  = threadIdx.x & 31;
    const int qslot = blockIdx.x * WPB + warp;
    const int b     = qslot >> 13;
    const int s     = qslot & (N_CONST - 1);

    const float4 me = g_sorted[b * N_CONST + s];     // broadcast across warp
    const float qx = me.x, qy = me.y, qz = me.z;
    const int   qi = __float_as_int(me.w);

    const int cx = min(max((int)(qx * (float)GRID), 0), GRID - 1);
    const int cy = min(max((int)(qy * (float)GRID), 0), GRID - 1);
    const int cz = min(max((int)(qz * (float)GRID), 0), GRID - 1);
    const int x0 = max(cx - 1, 0), x1 = min(cx + 1, GRID - 1);
    const int w  = x1 - x0 + 1;

    const int*    startb  = g_start  + b * (NCELLS + 1);
    const float4* sortedb = g_sorted + b * N_CONST;

    // slab distances^2 for the 3 y-rows and 3 z-slabs
    float dy2[3], dz2[3];
#pragma unroll
    for (int d = 0; d < 3; ++d) {
        float ry = (cy + d - 1) * 0.1f;
        float rz = (cz + d - 1) * 0.1f;
        float dyv = fmaxf(fmaxf(ry - qy, qy - (ry + 0.1f)), 0.0f);
        float dzv = fmaxf(fmaxf(rz - qz, qz - (rz + 0.1f)), 0.0f);
        dy2[d] = dyv * dyv;
        dz2[d] = dzv * dzv;
    }

    // per-lane sorted-4 smallest keys
    unsigned s0 = 0xFFFFFFFFu, s1 = 0xFFFFFFFFu, s2 = 0xFFFFFFFFu, s3 = 0xFFFFFFFFu;

#pragma unroll
    for (int dzc = 0; dzc < 3; ++dzc) {
#pragma unroll
        for (int dyc = 0; dyc < 3; ++dyc) {
            const int iyy = cy + dyc - 1, izz = cz + dzc - 1;
            if ((unsigned)iyy >= GRID || (unsigned)izz >= GRID) continue;   // uniform
            if (dy2[dyc] + dz2[dzc] > R2LIM) continue;                       // uniform

            const int c0  = x0 + GRID * (iyy + GRID * izz);
            const int beg = __ldg(startb + c0);
            const int end = __ldg(startb + c0 + w);
            for (int p0 = beg; p0 < end; p0 += 32) {                        // uniform
                const int p = p0 + lane;
                unsigned kk = 0xFFFFFFFFu;
                if (p < end) {
                    float4 a = __ldg(sortedb + p);
                    float dx = qx - a.x, dy = qy - a.y, dz = qz - a.z;
                    float d2 = fmaf(dx, dx, fmaf(dy, dy, dz * dz));
                    if (d2 <= R2LIM)
                        kk = ((unsigned)(d2 * D2SCALE) << 13)
                           | (unsigned)__float_as_int(a.w);
                }
                // branchless insert into sorted-4 (7 IMNMX)
                unsigned a0 = min(s0, kk), b0 = max(s0, kk);
                unsigned c1 = min(s1, b0), d1 = max(s1, b0);
                unsigned e2 = min(s2, d1), f2 = max(s2, d1);
                s3 = min(s3, f2);
                s0 = a0; s1 = c1; s2 = e2;
            }
        }
    }

    // prefetch own mask row (address known) — overlaps the REDUX chain below
    const float* maskb = mask + (size_t)b * N_CONST * KS_CONST;
    const float4* mrow = reinterpret_cast<const float4*>(maskb + (size_t)qi * KS_CONST);
    float4 m0, m1, m2, m3;
    if (lane < 8) {
        m0 = __ldg(mrow);     m1 = __ldg(mrow + 1);
        m2 = __ldg(mrow + 2); m3 = __ldg(mrow + 3);
    }

    // ---- extract global top-8 via REDUX.MIN; winner r lands on lane r ----
    unsigned mykey = 0xFFFFFFFFu;
#pragma unroll
    for (int r = 0; r < 8; ++r) {
        unsigned wv = __reduce_min_sync(0xFFFFFFFFu, s0);
        if (lane == r) mykey = wv;
        bool own = (s0 == wv) && (wv != 0xFFFFFFFFu);
        s0 = own ? s1 : s0;
        s1 = own ? s2 : s1;
        s2 = own ? s3 : s2;
        s3 = own ? 0xFFFFFFFFu : s3;
    }

    // ---- loss terms: lanes 0-7 gather their neighbor's mask row ----
    float term = 0.0f;
    if (lane < 8 && mykey != 0xFFFFFFFFu) {
        unsigned uq = mykey >> 13;
        int      nb = (int)(mykey & 8191u);
        if (uq <= RTHRESH_U && nb != qi) {       // in radius, not self
            const float4* nrow = reinterpret_cast<const float4*>(maskb + (size_t)nb * KS_CONST);
            float4 n0 = __ldg(nrow), n1 = __ldg(nrow + 1), n2 = __ldg(nrow + 2), n3 = __ldg(nrow + 3);
            term  = fabsf(m0.x - n0.x) + fabsf(m0.y - n0.y) + fabsf(m0.z - n0.z) + fabsf(m0.w - n0.w);
            term += fabsf(m1.x - n1.x) + fabsf(m1.y - n1.y) + fabsf(m1.z - n1.z) + fabsf(m1.w - n1.w);
            term += fabsf(m2.x - n2.x) + fabsf(m2.y - n2.y) + fabsf(m2.z - n2.z) + fabsf(m2.w - n2.w);
            term += fabsf(m3.x - n3.x) + fabsf(m3.y - n3.y) + fabsf(m3.z - n3.z) + fabsf(m3.w - n3.w);
        }
    }
    // fixed shfl tree (deterministic association, lanes >= 8 contribute 0)
    term += __shfl_down_sync(0xFFFFFFFFu, term, 16);
    term += __shfl_down_sync(0xFFFFFFFFu, term, 8);
    term += __shfl_down_sync(0xFFFFFFFFu, term, 4);
    term += __shfl_down_sync(0xFFFFFFFFu, term, 2);
    term += __shfl_down_sync(0xFFFFFFFFu, term, 1);
    if (lane == 0) swacc[warp] = term;

    // ---- deterministic block + grid reduction ----
    __syncthreads();
    if (threadIdx.x == 0) {
        float acc = swacc[0] + swacc[1];
        g_partials[blockIdx.x] = acc;
        __threadfence();
        int old = atomicAdd(&g_done, 1);
        slast = (old == MAIN_BLOCKS - 1) ? 1 : 0;
    }
    __syncthreads();
    if (slast) {
        int tid = threadIdx.x;
        float v = 0.0f;
#pragma unroll
        for (int j = 0; j < MAIN_BLOCKS / MAIN_TPB; ++j)
            v += __ldcg(&g_partials[tid + j * MAIN_TPB]);
        sred[tid] = v;
        __syncthreads();
#pragma unroll
        for (int r = MAIN_TPB / 2; r > 0; r >>= 1) {
            if (tid < r) sred[tid] += sred[tid + r];
            __syncthreads();
        }
        if (tid == 0)
            out[0] = sred[0] / (float)(TOTPTS * 8);
    }
}

extern "C" void kernel_launch(void* const* d_in, const int* in_sizes, int n_in,
                              void* d_out, int out_size) {
    const float* pc   = (const float*)d_in[0];   // (2, 8192, 3)  f32
    const float* mask = (const float*)d_in[1];   // (2, 8192, 16) f32
    float* out = (float*)d_out;                  // scalar f32

    k_build<<<B_CONST, BUILD_TPB>>>(pc);
    knn_loss_main<<<MAIN_BLOCKS, MAIN_TPB>>>(mask, out);
}

// round 8
// speedup vs baseline: 1.1106x; 1.1106x over previous
#include <cuda_runtime.h>
#include <math.h>

// KnnLoss via spatial grid, warp-per-query, register-resident top-8 selection.
// B=2, N=8192 pts uniform in [0,1]^3, KS=16, K=8, radius 0.1.
// Neighbors with dist > 0.1 are replaced by self => contribute 0, so a
// 10x10x10 grid (cell = radius) holds everything that matters.
// Keys: 18-bit fixed-point d2 (monotone quantization of [0, 0.0101]) << 13 | idx.
// (d2, lowest-idx) order == jax.lax.top_k stable rule up to a 3.9e-8 d2 granule.
// Selection: per-lane sorted-4 list + 8 rounds of __reduce_min_sync (REDUX.MIN).
// Deterministic: extraction order is the unique sorted order; sums use fixed trees.

#define B_CONST 2
#define N_CONST 8192
#define KS_CONST 16
#define GRID 10
#define NCELLS (GRID * GRID * GRID)               // 1000
#define TOTPTS (B_CONST * N_CONST)                // 16384
#define R2LIM 0.0101f
#define D2SCALE 25900000.0f                        // 0.0101 * SCALE = 261590 < 2^18
#define RTHRESH_U 259000u                          // floor(0.01 * SCALE)
#define WPB 4                                      // warps (queries) per block
#define MAIN_TPB 128
#define MAIN_BLOCKS (TOTPTS / WPB)                // 4096
#define BUILD_TPB 1024
#define PTS_PER_THREAD (N_CONST / BUILD_TPB)      // 8

__device__ int    g_start [B_CONST * (NCELLS + 1)];
__device__ float4 g_sorted[TOTPTS];               // (x, y, z, idx-as-float-bits)
__device__ float  g_partials[MAIN_BLOCKS];
__device__ int    g_done;

__device__ __forceinline__ int cell_of(float x, float y, float z) {
    int cx = min(max((int)(x * (float)GRID), 0), GRID - 1);
    int cy = min(max((int)(y * (float)GRID), 0), GRID - 1);
    int cz = min(max((int)(z * (float)GRID), 0), GRID - 1);
    return cx + GRID * (cy + GRID * cz);          // x fastest
}

// ---------------- fused grid build: one block per batch ----------------

__global__ __launch_bounds__(BUILD_TPB) void k_build(const float* __restrict__ pc) {
    __shared__ int scnt[BUILD_TPB];
    __shared__ int swoff[32];
    __shared__ int scur[NCELLS];

    const int b    = blockIdx.x;
    const int tid  = threadIdx.x;
    const int lane = tid & 31;
    const int wid  = tid >> 5;
    const float* pcb = pc + (size_t)b * N_CONST * 3;

    scnt[tid] = 0;
    __syncthreads();

    // one global read pass; keep points + cells in registers for the scatter
    float px[PTS_PER_THREAD], py[PTS_PER_THREAD], pz[PTS_PER_THREAD];
    int   pcell[PTS_PER_THREAD];
#pragma unroll
    for (int k = 0; k < PTS_PER_THREAD; ++k) {
        int i = tid + k * BUILD_TPB;
        px[k] = __ldg(pcb + 3 * i + 0);
        py[k] = __ldg(pcb + 3 * i + 1);
        pz[k] = __ldg(pcb + 3 * i + 2);
        pcell[k] = cell_of(px[k], py[k], pz[k]);
    }
#pragma unroll
    for (int k = 0; k < PTS_PER_THREAD; ++k)
        atomicAdd(&scnt[pcell[k]], 1);
    __syncthreads();

    int c = scnt[tid];
    int v = c;
#pragma unroll
    for (int o = 1; o < 32; o <<= 1) {
        int n = __shfl_up_sync(0xFFFFFFFFu, v, o);
        if (lane >= o) v += n;
    }
    if (lane == 31) swoff[wid] = v;
    __syncthreads();
    if (wid == 0) {
        int w = swoff[lane];
#pragma unroll
        for (int o = 1; o < 32; o <<= 1) {
            int n = __shfl_up_sync(0xFFFFFFFFu, w, o);
            if (lane >= o) w += n;
        }
        swoff[lane] = w;
    }
    __syncthreads();
    int incl = v + (wid ? swoff[wid - 1] : 0);
    int excl = incl - c;
    if (tid < NCELLS) {
        g_start[b * (NCELLS + 1) + tid] = excl;
        scur[tid] = excl;
    }
    if (tid == NCELLS - 1) g_start[b * (NCELLS + 1) + NCELLS] = incl;
    if (b == 0 && tid == 0) g_done = 0;
    __syncthreads();

#pragma unroll
    for (int k = 0; k < PTS_PER_THREAD; ++k) {
        int i = tid + k * BUILD_TPB;
        int pos = atomicAdd(&scur[pcell[k]], 1);
        g_sorted[b * N_CONST + pos] = make_float4(px[k], py[k], pz[k], __int_as_float(i));
    }
}

// ---------------- main: warp-per-query knn + loss + fused finalize ----------------

__global__ __launch_bounds__(MAIN_TPB) void knn_loss_main(const float* __restrict__ mask,
                                                          float* __restrict__ out) {
    __shared__ float swacc[WPB];
    __shared__ float sred[MAIN_TPB];
    __shared__ int slast;

    const int warp  = threadIdx.x >> 5;
    const int lane  = threadIdx.x & 31;
    const int qslot = blockIdx.x * WPB + warp;
    const int b     = qslot >> 13;
    const int s     = qslot & (N_CONST - 1);

    const float4 me = g_sorted[b * N_CONST + s];     // broadcast across warp
    const float qx = me.x, qy = me.y, qz = me.z;
    const int   qi = __float_as_int(me.w);

    const int cx = min(max((int)(qx * (float)GRID), 0), GRID - 1);
    const int cy = min(max((int)(qy * (float)GRID), 0), GRID - 1);
    const int cz = min(max((int)(qz * (float)GRID), 0), GRID - 1);
    const int x0 = max(cx - 1, 0), x1 = min(cx + 1, GRID - 1);
    const int w  = x1 - x0 + 1;

    const int*    startb  = g_start  + b * (NCELLS + 1);
    const float4* sortedb = g_sorted + b * N_CONST;

    // slab distances^2 for the 3 y-rows and 3 z-slabs
    float dy2[3], dz2[3];
#pragma unroll
    for (int d = 0; d < 3; ++d) {
        float ry = (cy + d - 1) * 0.1f;
        float rz = (cz + d - 1) * 0.1f;
        float dyv = fmaxf(fmaxf(ry - qy, qy - (ry + 0.1f)), 0.0f);
        float dzv = fmaxf(fmaxf(rz - qz, qz - (rz + 0.1f)), 0.0f);
        dy2[d] = dyv * dyv;
        dz2[d] = dzv * dzv;
    }

    // per-lane sorted-4 smallest keys
    unsigned s0 = 0xFFFFFFFFu, s1 = 0xFFFFFFFFu, s2 = 0xFFFFFFFFu, s3 = 0xFFFFFFFFu;

#pragma unroll
    for (int dzc = 0; dzc < 3; ++dzc) {
#pragma unroll
        for (int dyc = 0; dyc < 3; ++dyc) {
            const int iyy = cy + dyc - 1, izz = cz + dzc - 1;
            if ((unsigned)iyy >= GRID || (unsigned)izz >= GRID) continue;   // uniform
            if (dy2[dyc] + dz2[dzc] > R2LIM) continue;                       // uniform

            const int c0  = x0 + GRID * (iyy + GRID * izz);
            const int beg = __ldg(startb + c0);
            const int end = __ldg(startb + c0 + w);
            for (int p0 = beg; p0 < end; p0 += 32) {                        // uniform
                const int p = p0 + lane;
                unsigned kk = 0xFFFFFFFFu;
                if (p < end) {
                    float4 a = __ldg(sortedb + p);
                    float dx = qx - a.x, dy = qy - a.y, dz = qz - a.z;
                    float d2 = fmaf(dx, dx, fmaf(dy, dy, dz * dz));
                    if (d2 <= R2LIM)
                        kk = ((unsigned)(d2 * D2SCALE) << 13)
                           | (unsigned)__float_as_int(a.w);
                }
                // branchless insert into sorted-4 (7 IMNMX)
                unsigned a0 = min(s0, kk), b0 = max(s0, kk);
                unsigned c1 = min(s1, b0), d1 = max(s1, b0);
                unsigned e2 = min(s2, d1), f2 = max(s2, d1);
                s3 = min(s3, f2);
                s0 = a0; s1 = c1; s2 = e2;
            }
        }
    }

    // prefetch own mask row (address known) — overlaps the REDUX chain below
    const float* maskb = mask + (size_t)b * N_CONST * KS_CONST;
    const float4* mrow = reinterpret_cast<const float4*>(maskb + (size_t)qi * KS_CONST);
    float4 m0, m1, m2, m3;
    if (lane < 8) {
        m0 = __ldg(mrow);     m1 = __ldg(mrow + 1);
        m2 = __ldg(mrow + 2); m3 = __ldg(mrow + 3);
    }

    // ---- extract global top-8 via REDUX.MIN; winner r lands on lane r ----
    unsigned mykey = 0xFFFFFFFFu;
#pragma unroll
    for (int r = 0; r < 8; ++r) {
        unsigned wv = __reduce_min_sync(0xFFFFFFFFu, s0);
        if (lane == r) mykey = wv;
        bool own = (s0 == wv) && (wv != 0xFFFFFFFFu);
        s0 = own ? s1 : s0;
        s1 = own ? s2 : s1;
        s2 = own ? s3 : s2;
        s3 = own ? 0xFFFFFFFFu : s3;
    }

    // ---- loss terms: lanes 0-7 gather their neighbor's mask row ----
    float term = 0.0f;
    if (lane < 8 && mykey != 0xFFFFFFFFu) {
        unsigned uq = mykey >> 13;
        int      nb = (int)(mykey & 8191u);
        if (uq <= RTHRESH_U && nb != qi) {       // in radius, not self
            const float4* nrow = reinterpret_cast<const float4*>(maskb + (size_t)nb * KS_CONST);
            float4 n0 = __ldg(nrow), n1 = __ldg(nrow + 1), n2 = __ldg(nrow + 2), n3 = __ldg(nrow + 3);
            term  = fabsf(m0.x - n0.x) + fabsf(m0.y - n0.y) + fabsf(m0.z - n0.z) + fabsf(m0.w - n0.w);
            term += fabsf(m1.x - n1.x) + fabsf(m1.y - n1.y) + fabsf(m1.z - n1.z) + fabsf(m1.w - n1.w);
            term += fabsf(m2.x - n2.x) + fabsf(m2.y - n2.y) + fabsf(m2.z - n2.z) + fabsf(m2.w - n2.w);
            term += fabsf(m3.x - n3.x) + fabsf(m3.y - n3.y) + fabsf(m3.z - n3.z) + fabsf(m3.w - n3.w);
        }
    }
    // fixed shfl tree (deterministic association, lanes >= 8 contribute 0)
    term += __shfl_down_sync(0xFFFFFFFFu, term, 16);
    term += __shfl_down_sync(0xFFFFFFFFu, term, 8);
    term += __shfl_down_sync(0xFFFFFFFFu, term, 4);
    term += __shfl_down_sync(0xFFFFFFFFu, term, 2);
    term += __shfl_down_sync(0xFFFFFFFFu, term, 1);
    if (lane == 0) swacc[warp] = term;

    // ---- deterministic block + grid reduction ----
    __syncthreads();
    if (threadIdx.x == 0) {
        float acc = (swacc[0] + swacc[1]) + (swacc[2] + swacc[3]);
        g_partials[blockIdx.x] = acc;
        __threadfence();
        int old = atomicAdd(&g_done, 1);
        slast = (old == MAIN_BLOCKS - 1) ? 1 : 0;
    }
    __syncthreads();
    if (slast) {
        int tid = threadIdx.x;
        float v = 0.0f;
#pragma unroll
        for (int j = 0; j < MAIN_BLOCKS / MAIN_TPB; ++j)
            v += __ldcg(&g_partials[tid + j * MAIN_TPB]);
        sred[tid] = v;
        __syncthreads();
#pragma unroll
        for (int r = MAIN_TPB / 2; r > 0; r >>= 1) {
            if (tid < r) sred[tid] += sred[tid + r];
            __syncthreads();
        }
        if (tid == 0)
            out[0] = sred[0] / (float)(TOTPTS * 8);
    }
}

extern "C" void kernel_launch(void* const* d_in, const int* in_sizes, int n_in,
                              void* d_out, int out_size) {
    const float* pc   = (const float*)d_in[0];   // (2, 8192, 3)  f32
    const float* mask = (const float*)d_in[1];   // (2, 8192, 16) f32
    float* out = (float*)d_out;                  // scalar f32

    k_build<<<B_CONST, BUILD_TPB>>>(pc);
    knn_loss_main<<<MAIN_BLOCKS, MAIN_TPB>>>(mask, out);
}